// round 10
// baseline (speedup 1.0000x reference)
#include <cuda_runtime.h>
#include <math.h>

#define TGT 2048
#define BSZ 4
#define E   1024
#define H   16
#define HD  64
#define M1  (TGT*BSZ)   // 8192 rows of [T,B,*]
#define NBH (BSZ*H)     // 64 (b,h) pairs

// ---- scratch (static device globals; no allocation allowed) ----
__device__ float g_q[(size_t)NBH*TGT*HD];     // [B,H,T,HD]
__device__ float g_k[(size_t)NBH*TGT*HD];
__device__ float g_v[(size_t)NBH*TGT*HD];
__device__ float g_ctx[(size_t)M1*E];         // [T,B,E]
__device__ float g_P[(size_t)NBH*TGT*TGT];    // [B,H,T,T] 1GiB

// ============================================================
// NT 128x128 tile, 256 threads, K-tile 16, 8x8 per thread.
// A,B row-major with K contiguous. C[m,n] = sum_k A[m,k]*B[n,k].
// k-accumulation order identical to the 64x64 baseline
// (sequential k0 then kk) -> bit-identical outputs.
// ============================================================

#define NT_TILE_BODY(APTR, LDA, BPTR, LDB, KTOT)                               \
    __shared__ __align__(16) float As[16][136];                                \
    __shared__ __align__(16) float Bs[16][136];                                \
    const int tid = threadIdx.x;                                               \
    const int lm  = tid >> 1;                                                  \
    const int lk  = (tid & 1) << 3;                                            \
    const int ty  = tid >> 4, tx = tid & 15;                                   \
    float acc[8][8] = {};                                                      \
    for (int k0 = 0; k0 < (KTOT); k0 += 16) {                                  \
        {                                                                      \
            const float4 a0 = *(const float4*)((APTR) + (size_t)(mBase + lm) * (LDA) + k0 + lk);     \
            const float4 a1 = *(const float4*)((APTR) + (size_t)(mBase + lm) * (LDA) + k0 + lk + 4); \
            const float4 b0 = *(const float4*)((BPTR) + (size_t)(nBase + lm) * (LDB) + k0 + lk);     \
            const float4 b1 = *(const float4*)((BPTR) + (size_t)(nBase + lm) * (LDB) + k0 + lk + 4); \
            As[lk+0][lm]=a0.x; As[lk+1][lm]=a0.y; As[lk+2][lm]=a0.z; As[lk+3][lm]=a0.w;              \
            As[lk+4][lm]=a1.x; As[lk+5][lm]=a1.y; As[lk+6][lm]=a1.z; As[lk+7][lm]=a1.w;              \
            Bs[lk+0][lm]=b0.x; Bs[lk+1][lm]=b0.y; Bs[lk+2][lm]=b0.z; Bs[lk+3][lm]=b0.w;              \
            Bs[lk+4][lm]=b1.x; Bs[lk+5][lm]=b1.y; Bs[lk+6][lm]=b1.z; Bs[lk+7][lm]=b1.w;              \
        }                                                                      \
        __syncthreads();                                                       \
        _Pragma("unroll")                                                      \
        for (int kk = 0; kk < 16; kk++) {                                      \
            const float4 av0 = *(const float4*)&As[kk][ty*8];                  \
            const float4 av1 = *(const float4*)&As[kk][ty*8+4];                \
            const float4 bv0 = *(const float4*)&Bs[kk][tx*8];                  \
            const float4 bv1 = *(const float4*)&Bs[kk][tx*8+4];                \
            const float a_[8] = {av0.x,av0.y,av0.z,av0.w,av1.x,av1.y,av1.z,av1.w}; \
            const float b_[8] = {bv0.x,bv0.y,bv0.z,bv0.w,bv1.x,bv1.y,bv1.z,bv1.w}; \
            _Pragma("unroll")                                                  \
            for (int i=0;i<8;i++)                                              \
                _Pragma("unroll")                                              \
                for (int j=0;j<8;j++)                                          \
                    acc[i][j] = fmaf(a_[i], b_[j], acc[i][j]);                 \
        }                                                                      \
        __syncthreads();                                                       \
    }

// ---- kernel 1: QKV projections (grid.z selects q/k/v) ----
__global__ __launch_bounds__(256) void qkv_kernel(
    const float* __restrict__ x,
    const float* __restrict__ wq, const float* __restrict__ bq,
    const float* __restrict__ wk, const float* __restrict__ bk,
    const float* __restrict__ wv, const float* __restrict__ bv)
{
    const int which = blockIdx.z;
    const float* w    = (which==0) ? wq : (which==1) ? wk : wv;
    const float* bias = (which==0) ? bq : (which==1) ? bk : bv;
    float* outp       = (which==0) ? g_q : (which==1) ? g_k : g_v;
    const float scale = (which==0) ? 0.125f : 1.0f;   // HD^-0.5

    const int mBase = blockIdx.y * 128, nBase = blockIdx.x * 128;
    NT_TILE_BODY(x, E, w, E, E)

    #pragma unroll
    for (int i=0;i<8;i++) {
        const int m = mBase + ty*8 + i;
        const int t = m >> 2, b = m & 3;           // m = t*BSZ + b
        #pragma unroll
        for (int j=0;j<8;j++) {
            const int n = nBase + tx*8 + j;
            const int h = n >> 6, d = n & 63;      // n = h*HD + d
            outp[((size_t)(b*H + h)*TGT + t)*HD + d] = (acc[i][j] + bias[n]) * scale;
        }
    }
}

// ---- kernel 2: scores[b,h,q,k] = <qh, kh>  (NT, K=HD=64) ----
__global__ __launch_bounds__(256) void scores_kernel()
{
    const int bh = blockIdx.z;
    const float* A  = g_q + (size_t)bh * TGT * HD;
    const float* Bm = g_k + (size_t)bh * TGT * HD;
    float* P = g_P + (size_t)bh * TGT * TGT;

    const int mBase = blockIdx.y * 128, nBase = blockIdx.x * 128;
    NT_TILE_BODY(A, HD, Bm, HD, HD)

    #pragma unroll
    for (int i=0;i<8;i++)
        #pragma unroll
        for (int j=0;j<8;j++)
            P[(size_t)(mBase + ty*8 + i) * TGT + nBase + tx*8 + j] = acc[i][j];
}

// ---- kernel 3: row softmax of P (in place) + head-avg output (unchanged) ----
__global__ __launch_bounds__(256) void softmax_avg_kernel(float* __restrict__ avg_out)
{
    const int t = blockIdx.x, b = blockIdx.y;
    const int tid = threadIdx.x;
    __shared__ float sred[8];

    float accAvg[8];
    #pragma unroll
    for (int j=0;j<8;j++) accAvg[j] = 0.0f;

    for (int h = 0; h < H; h++) {
        float* row = g_P + ((size_t)((b*H + h)*TGT) + t) * TGT;
        float r[8];
        #pragma unroll
        for (int j=0;j<8;j++) r[j] = row[tid + j*256];

        float m = r[0];
        #pragma unroll
        for (int j=1;j<8;j++) m = fmaxf(m, r[j]);
        #pragma unroll
        for (int o=16;o>0;o>>=1) m = fmaxf(m, __shfl_xor_sync(0xffffffffu, m, o));
        if ((tid & 31) == 0) sred[tid >> 5] = m;
        __syncthreads();
        if (tid < 32) {
            float w = (tid < 8) ? sred[tid] : -INFINITY;
            #pragma unroll
            for (int o=4;o>0;o>>=1) w = fmaxf(w, __shfl_xor_sync(0xffffffffu, w, o));
            if (tid == 0) sred[0] = w;
        }
        __syncthreads();
        m = sred[0];
        __syncthreads();

        float s = 0.0f;
        #pragma unroll
        for (int j=0;j<8;j++) { r[j] = __expf(r[j] - m); s += r[j]; }
        #pragma unroll
        for (int o=16;o>0;o>>=1) s += __shfl_xor_sync(0xffffffffu, s, o);
        if ((tid & 31) == 0) sred[tid >> 5] = s;
        __syncthreads();
        if (tid < 32) {
            float w = (tid < 8) ? sred[tid] : 0.0f;
            #pragma unroll
            for (int o=4;o>0;o>>=1) w += __shfl_xor_sync(0xffffffffu, w, o);
            if (tid == 0) sred[0] = w;
        }
        __syncthreads();
        s = sred[0];
        __syncthreads();

        const float inv = 1.0f / s;
        #pragma unroll
        for (int j=0;j<8;j++) {
            const float p = r[j] * inv;
            row[tid + j*256] = p;
            accAvg[j] += p;
        }
    }
    const float invH = 1.0f / (float)H;
    #pragma unroll
    for (int j=0;j<8;j++)
        avg_out[((size_t)b*TGT + t)*TGT + tid + j*256] = accAvg[j] * invH;
}

// ---- kernel 4: ctx = P @ V  (NN, K=TGT, N=HD=64) -> [T,B,E] ----
// tile 128(m) x 64(n), 8x4 per thread, K-tile 16
__global__ __launch_bounds__(256) void ctx_kernel()
{
    const int bh = blockIdx.z;
    const int b = bh / H, h = bh % H;
    const float* P = g_P + (size_t)bh * TGT * TGT;
    const float* V = g_v + (size_t)bh * TGT * HD;

    __shared__ __align__(16) float As[16][136];
    __shared__ __align__(16) float Bs[16][68];

    const int tid = threadIdx.x;
    const int lm  = tid >> 1;          // 0..127
    const int lk  = (tid & 1) << 3;    // 0 or 8
    const int vk  = tid >> 4;          // 0..15
    const int vn  = (tid & 15) << 2;   // 0..60
    const int ty  = tid >> 4, tx = tid & 15;
    const int mBase = blockIdx.x * 128;

    float acc[8][4] = {};
    for (int k0 = 0; k0 < TGT; k0 += 16) {
        {
            const float4 a0 = *(const float4*)(P + (size_t)(mBase + lm) * TGT + k0 + lk);
            const float4 a1 = *(const float4*)(P + (size_t)(mBase + lm) * TGT + k0 + lk + 4);
            As[lk+0][lm]=a0.x; As[lk+1][lm]=a0.y; As[lk+2][lm]=a0.z; As[lk+3][lm]=a0.w;
            As[lk+4][lm]=a1.x; As[lk+5][lm]=a1.y; As[lk+6][lm]=a1.z; As[lk+7][lm]=a1.w;
            *(float4*)&Bs[vk][vn] = *(const float4*)(V + (size_t)(k0 + vk) * HD + vn);
        }
        __syncthreads();
        #pragma unroll
        for (int kk = 0; kk < 16; kk++) {
            const float4 av0 = *(const float4*)&As[kk][ty*8];
            const float4 av1 = *(const float4*)&As[kk][ty*8+4];
            const float4 bv  = *(const float4*)&Bs[kk][tx*4];
            const float a_[8] = {av0.x,av0.y,av0.z,av0.w,av1.x,av1.y,av1.z,av1.w};
            const float b_[4] = {bv.x,bv.y,bv.z,bv.w};
            #pragma unroll
            for (int i=0;i<8;i++)
                #pragma unroll
                for (int j=0;j<4;j++)
                    acc[i][j] = fmaf(a_[i], b_[j], acc[i][j]);
        }
        __syncthreads();
    }
    #pragma unroll
    for (int i=0;i<8;i++) {
        const int q = mBase + ty*8 + i;   // = t
        #pragma unroll
        for (int j=0;j<4;j++) {
            const int d = tx*4 + j;
            g_ctx[((size_t)q*BSZ + b)*E + h*HD + d] = acc[i][j];
        }
    }
}

// ---- kernel 5: out = ctx @ wo^T + bo  (NT) ----
__global__ __launch_bounds__(256) void outproj_kernel(
    const float* __restrict__ wo, const float* __restrict__ bo,
    float* __restrict__ out)
{
    const int mBase = blockIdx.y * 128, nBase = blockIdx.x * 128;
    NT_TILE_BODY(g_ctx, E, wo, E, E)

    #pragma unroll
    for (int i=0;i<8;i++) {
        const int m = mBase + ty*8 + i;
        #pragma unroll
        for (int j=0;j<8;j++) {
            const int n = nBase + tx*8 + j;
            out[(size_t)m*E + n] = acc[i][j] + bo[n];
        }
    }
}

extern "C" void kernel_launch(void* const* d_in, const int* in_sizes, int n_in,
                              void* d_out, int out_size)
{
    (void)in_sizes; (void)n_in; (void)out_size;
    const float* query = (const float*)d_in[0];
    const float* wq = (const float*)d_in[1];
    const float* bq = (const float*)d_in[2];
    const float* wk = (const float*)d_in[3];
    const float* bk = (const float*)d_in[4];
    const float* wv = (const float*)d_in[5];
    const float* bv = (const float*)d_in[6];
    const float* wo = (const float*)d_in[7];
    const float* bo = (const float*)d_in[8];

    float* out = (float*)d_out;                       // [T,B,E]
    float* avg = out + (size_t)TGT*BSZ*E;             // [B,T,T]

    dim3 t256(256);
    qkv_kernel<<<dim3(E/128, M1/128, 3), t256>>>(query, wq, bq, wk, bk, wv, bv);
    scores_kernel<<<dim3(TGT/128, TGT/128, NBH), t256>>>();
    softmax_avg_kernel<<<dim3(TGT, BSZ), t256>>>(avg);
    ctx_kernel<<<dim3(TGT/128, 1, NBH), t256>>>();
    outproj_kernel<<<dim3(E/128, M1/128, 1), t256>>>(wo, bo, out);
}

// round 13
// speedup vs baseline: 1.4253x; 1.4253x over previous
#include <cuda_runtime.h>
#include <mma.h>
#include <math.h>

using namespace nvcuda;

#define TGT 2048
#define BSZ 4
#define E   1024
#define H   16
#define HD  64
#define M1  (TGT*BSZ)   // 8192
#define NBH (BSZ*H)     // 64

// ---- scratch (static device globals; no allocation allowed) ----
__device__ float g_q[(size_t)NBH*TGT*HD];       // [B,H,T,HD]
__device__ float g_k[(size_t)NBH*TGT*HD];
__device__ float g_v[(size_t)NBH*TGT*HD];
__device__ float g_ctx[(size_t)M1*E];           // [T,B,E]
__device__ float g_P[(size_t)NBH*TGT*TGT];      // [B,H,T,T] 1GiB
__device__ float g_tmp[(size_t)3*M1*E];         // raw GEMM staging (100MB)

// ============================================================
// tf32 WMMA NT GEMM: C[m,n] = sum_k A[m,k]*B[n,k]
// block tile 128x128, K-tile 32, 256 threads = 8 warps (4M x 2N),
// warp tile 32x64 = 2x4 frags of m16n16k8.
// Inputs rounded to tf32 on smem store (wmma::__float_to_tf32).
// ============================================================

#define MMA_NT_LOOP(APTR, LDA, BPTR, LDB, KTOT)                                 \
    __shared__ __align__(16) float As[128][40];                                 \
    __shared__ __align__(16) float Bs[128][40];                                 \
    const int tid  = threadIdx.x;                                               \
    const int warp = tid >> 5;                                                  \
    const int wm   = warp & 3;       /* m0 = wm*32 */                           \
    const int wn   = warp >> 2;      /* n0 = wn*64 */                           \
    const int lr   = tid >> 1;       /* loader row 0..127 */                    \
    const int lc   = (tid & 1) << 4; /* 0 or 16 */                              \
    wmma::fragment<wmma::accumulator,16,16,8,float> acc[2][4];                  \
    _Pragma("unroll")                                                           \
    for (int i=0;i<2;i++)                                                       \
        _Pragma("unroll")                                                       \
        for (int j=0;j<4;j++) wmma::fill_fragment(acc[i][j], 0.0f);             \
    for (int k0 = 0; k0 < (KTOT); k0 += 32) {                                   \
        _Pragma("unroll")                                                       \
        for (int q = 0; q < 4; q++) {                                           \
            const float4 av = *(const float4*)((APTR) + (size_t)(mBase+lr)*(LDA) + k0 + lc + q*4); \
            As[lr][lc+q*4+0] = wmma::__float_to_tf32(av.x);                     \
            As[lr][lc+q*4+1] = wmma::__float_to_tf32(av.y);                     \
            As[lr][lc+q*4+2] = wmma::__float_to_tf32(av.z);                     \
            As[lr][lc+q*4+3] = wmma::__float_to_tf32(av.w);                     \
            const float4 bv = *(const float4*)((BPTR) + (size_t)(nBase+lr)*(LDB) + k0 + lc + q*4); \
            Bs[lr][lc+q*4+0] = wmma::__float_to_tf32(bv.x);                     \
            Bs[lr][lc+q*4+1] = wmma::__float_to_tf32(bv.y);                     \
            Bs[lr][lc+q*4+2] = wmma::__float_to_tf32(bv.z);                     \
            Bs[lr][lc+q*4+3] = wmma::__float_to_tf32(bv.w);                     \
        }                                                                       \
        __syncthreads();                                                        \
        _Pragma("unroll")                                                       \
        for (int kk = 0; kk < 32; kk += 8) {                                    \
            wmma::fragment<wmma::matrix_a,16,16,8,wmma::precision::tf32,wmma::row_major> af[2]; \
            wmma::fragment<wmma::matrix_b,16,16,8,wmma::precision::tf32,wmma::col_major> bf[4]; \
            _Pragma("unroll")                                                   \
            for (int i=0;i<2;i++) wmma::load_matrix_sync(af[i], &As[wm*32+i*16][kk], 40); \
            _Pragma("unroll")                                                   \
            for (int j=0;j<4;j++) wmma::load_matrix_sync(bf[j], &Bs[wn*64+j*16][kk], 40); \
            _Pragma("unroll")                                                   \
            for (int i=0;i<2;i++)                                               \
                _Pragma("unroll")                                               \
                for (int j=0;j<4;j++)                                           \
                    wmma::mma_sync(acc[i][j], af[i], bf[j], acc[i][j]);         \
        }                                                                       \
        __syncthreads();                                                        \
    }

// ---- kernel 1a: QKV GEMM -> g_tmp (raw, row-major [M1][E] per matrix) ----
__global__ __launch_bounds__(256) void qkv_mma_kernel(
    const float* __restrict__ x,
    const float* __restrict__ wq, const float* __restrict__ wk,
    const float* __restrict__ wv)
{
    const int which = blockIdx.z;
    const float* w = (which==0) ? wq : (which==1) ? wk : wv;
    float* outp = g_tmp + (size_t)which * M1 * E;

    const int mBase = blockIdx.y * 128, nBase = blockIdx.x * 128;
    MMA_NT_LOOP(x, E, w, E, E)

    #pragma unroll
    for (int i=0;i<2;i++)
        #pragma unroll
        for (int j=0;j<4;j++)
            wmma::store_matrix_sync(
                outp + (size_t)(mBase + wm*32 + i*16)*E + nBase + wn*64 + j*16,
                acc[i][j], E, wmma::mem_row_major);
}

// ---- kernel 1b: QKV epilogue: bias + scale + scatter to [B,H,T,HD] ----
__global__ __launch_bounds__(256) void qkv_epi_kernel(
    const float* __restrict__ bq, const float* __restrict__ bk,
    const float* __restrict__ bv)
{
    const int which = blockIdx.z;
    const float* bias = (which==0) ? bq : (which==1) ? bk : bv;
    const float* tmp  = g_tmp + (size_t)which * M1 * E;
    float* outp       = (which==0) ? g_q : (which==1) ? g_k : g_v;
    const float scale = (which==0) ? 0.125f : 1.0f;   // HD^-0.5

    const int idx = (blockIdx.x * 256 + threadIdx.x) * 4;   // multiple of 4
    const int m = idx / E, n = idx % E;
    const int t = m >> 2, b = m & 3;          // m = t*BSZ + b
    const int h = n >> 6, d = n & 63;         // 4 consecutive d, same head

    const float4 v4 = *(const float4*)(tmp + (size_t)m*E + n);
    const float4 b4 = *(const float4*)(bias + n);
    float4 o4;
    o4.x = (v4.x + b4.x) * scale;
    o4.y = (v4.y + b4.y) * scale;
    o4.z = (v4.z + b4.z) * scale;
    o4.w = (v4.w + b4.w) * scale;
    *(float4*)(outp + ((size_t)(b*H + h)*TGT + t)*HD + d) = o4;
}

// ---- kernel 2: scores = q @ k^T per (b,h), direct store to g_P ----
__global__ __launch_bounds__(256) void scores_mma_kernel()
{
    const int bh = blockIdx.z;
    const float* A  = g_q + (size_t)bh * TGT * HD;
    const float* Bm = g_k + (size_t)bh * TGT * HD;
    float* P = g_P + (size_t)bh * TGT * TGT;

    const int mBase = blockIdx.y * 128, nBase = blockIdx.x * 128;
    MMA_NT_LOOP(A, HD, Bm, HD, HD)

    #pragma unroll
    for (int i=0;i<2;i++)
        #pragma unroll
        for (int j=0;j<4;j++)
            wmma::store_matrix_sync(
                P + (size_t)(mBase + wm*32 + i*16)*TGT + nBase + wn*64 + j*16,
                acc[i][j], TGT, wmma::mem_row_major);
}

// ---- kernel 3: row softmax of P (in place) + head-avg (unchanged) ----
__global__ __launch_bounds__(256) void softmax_avg_kernel(float* __restrict__ avg_out)
{
    const int t = blockIdx.x, b = blockIdx.y;
    const int tid = threadIdx.x;
    __shared__ float sred[8];

    float accAvg[8];
    #pragma unroll
    for (int j=0;j<8;j++) accAvg[j] = 0.0f;

    for (int h = 0; h < H; h++) {
        float* row = g_P + ((size_t)((b*H + h)*TGT) + t) * TGT;
        float r[8];
        #pragma unroll
        for (int j=0;j<8;j++) r[j] = row[tid + j*256];

        float m = r[0];
        #pragma unroll
        for (int j=1;j<8;j++) m = fmaxf(m, r[j]);
        #pragma unroll
        for (int o=16;o>0;o>>=1) m = fmaxf(m, __shfl_xor_sync(0xffffffffu, m, o));
        if ((tid & 31) == 0) sred[tid >> 5] = m;
        __syncthreads();
        if (tid < 32) {
            float w = (tid < 8) ? sred[tid] : -INFINITY;
            #pragma unroll
            for (int o=4;o>0;o>>=1) w = fmaxf(w, __shfl_xor_sync(0xffffffffu, w, o));
            if (tid == 0) sred[0] = w;
        }
        __syncthreads();
        m = sred[0];
        __syncthreads();

        float s = 0.0f;
        #pragma unroll
        for (int j=0;j<8;j++) { r[j] = __expf(r[j] - m); s += r[j]; }
        #pragma unroll
        for (int o=16;o>0;o>>=1) s += __shfl_xor_sync(0xffffffffu, s, o);
        if ((tid & 31) == 0) sred[tid >> 5] = s;
        __syncthreads();
        if (tid < 32) {
            float w = (tid < 8) ? sred[tid] : 0.0f;
            #pragma unroll
            for (int o=4;o>0;o>>=1) w += __shfl_xor_sync(0xffffffffu, w, o);
            if (tid == 0) sred[0] = w;
        }
        __syncthreads();
        s = sred[0];
        __syncthreads();

        const float inv = 1.0f / s;
        #pragma unroll
        for (int j=0;j<8;j++) {
            const float p = r[j] * inv;
            row[tid + j*256] = p;
            accAvg[j] += p;
        }
    }
    const float invH = 1.0f / (float)H;
    #pragma unroll
    for (int j=0;j<8;j++)
        avg_out[((size_t)b*TGT + t)*TGT + tid + j*256] = accAvg[j] * invH;
}

// ---- kernel 4: ctx = P @ V  (NN, K=TGT, N=HD=64), direct store ----
// tile 128(m) x 64(n), K-tile 32; 8 warps = 4M x 2N, warp 32x32 = 2x2 frags
__global__ __launch_bounds__(256) void ctx_mma_kernel()
{
    const int bh = blockIdx.z;
    const int b = bh / H, h = bh % H;
    const float* P = g_P + (size_t)bh * TGT * TGT;
    const float* V = g_v + (size_t)bh * TGT * HD;

    __shared__ __align__(16) float As[128][40];
    __shared__ __align__(16) float Bs[32][72];

    const int tid  = threadIdx.x;
    const int warp = tid >> 5;
    const int wm   = warp & 3;        // m0 = wm*32
    const int wn   = warp >> 2;       // n0 = wn*32
    const int lr   = tid >> 1;        // A loader row 0..127
    const int lc   = (tid & 1) << 4;  // 0 or 16
    const int vk   = tid >> 3;        // V loader row 0..31
    const int vn   = (tid & 7) << 3;  // V loader col 0,8,...,56
    const int mBase = blockIdx.x * 128;

    wmma::fragment<wmma::accumulator,16,16,8,float> acc[2][2];
    #pragma unroll
    for (int i=0;i<2;i++)
        #pragma unroll
        for (int j=0;j<2;j++) wmma::fill_fragment(acc[i][j], 0.0f);

    for (int k0 = 0; k0 < TGT; k0 += 32) {
        #pragma unroll
        for (int q = 0; q < 4; q++) {
            const float4 av = *(const float4*)(P + (size_t)(mBase+lr)*TGT + k0 + lc + q*4);
            As[lr][lc+q*4+0] = wmma::__float_to_tf32(av.x);
            As[lr][lc+q*4+1] = wmma::__float_to_tf32(av.y);
            As[lr][lc+q*4+2] = wmma::__float_to_tf32(av.z);
            As[lr][lc+q*4+3] = wmma::__float_to_tf32(av.w);
        }
        #pragma unroll
        for (int q = 0; q < 2; q++) {
            const float4 bv = *(const float4*)(V + (size_t)(k0+vk)*HD + vn + q*4);
            Bs[vk][vn+q*4+0] = wmma::__float_to_tf32(bv.x);
            Bs[vk][vn+q*4+1] = wmma::__float_to_tf32(bv.y);
            Bs[vk][vn+q*4+2] = wmma::__float_to_tf32(bv.z);
            Bs[vk][vn+q*4+3] = wmma::__float_to_tf32(bv.w);
        }
        __syncthreads();
        #pragma unroll
        for (int kk = 0; kk < 32; kk += 8) {
            wmma::fragment<wmma::matrix_a,16,16,8,wmma::precision::tf32,wmma::row_major> af[2];
            wmma::fragment<wmma::matrix_b,16,16,8,wmma::precision::tf32,wmma::row_major> bf[2];
            #pragma unroll
            for (int i=0;i<2;i++) wmma::load_matrix_sync(af[i], &As[wm*32+i*16][kk], 40);
            #pragma unroll
            for (int j=0;j<2;j++) wmma::load_matrix_sync(bf[j], &Bs[kk][wn*32+j*16], 72);
            #pragma unroll
            for (int i=0;i<2;i++)
                #pragma unroll
                for (int j=0;j<2;j++)
                    wmma::mma_sync(acc[i][j], af[i], bf[j], acc[i][j]);
        }
        __syncthreads();
    }
    // store: g_ctx[(q*BSZ+b)*E + h*HD + d], row stride BSZ*E
    #pragma unroll
    for (int i=0;i<2;i++)
        #pragma unroll
        for (int j=0;j<2;j++)
            wmma::store_matrix_sync(
                g_ctx + ((size_t)(mBase + wm*32 + i*16)*BSZ + b)*E + h*HD + wn*32 + j*16,
                acc[i][j], BSZ*E, wmma::mem_row_major);
}

// ---- kernel 5a: outproj GEMM -> g_tmp[0] raw ----
__global__ __launch_bounds__(256) void outproj_mma_kernel(const float* __restrict__ wo)
{
    float* outp = g_tmp;
    const int mBase = blockIdx.y * 128, nBase = blockIdx.x * 128;
    MMA_NT_LOOP(g_ctx, E, wo, E, E)

    #pragma unroll
    for (int i=0;i<2;i++)
        #pragma unroll
        for (int j=0;j<4;j++)
            wmma::store_matrix_sync(
                outp + (size_t)(mBase + wm*32 + i*16)*E + nBase + wn*64 + j*16,
                acc[i][j], E, wmma::mem_row_major);
}

// ---- kernel 5b: outproj epilogue: + bias -> out ----
__global__ __launch_bounds__(256) void outproj_epi_kernel(
    const float* __restrict__ bo, float* __restrict__ out)
{
    const int idx = (blockIdx.x * 256 + threadIdx.x) * 4;
    const int n = idx % E;
    const float4 v4 = *(const float4*)(g_tmp + idx);
    const float4 b4 = *(const float4*)(bo + n);
    float4 o4;
    o4.x = v4.x + b4.x; o4.y = v4.y + b4.y;
    o4.z = v4.z + b4.z; o4.w = v4.w + b4.w;
    *(float4*)(out + idx) = o4;
}

extern "C" void kernel_launch(void* const* d_in, const int* in_sizes, int n_in,
                              void* d_out, int out_size)
{
    (void)in_sizes; (void)n_in; (void)out_size;
    const float* query = (const float*)d_in[0];
    const float* wq = (const float*)d_in[1];
    const float* bq = (const float*)d_in[2];
    const float* wk = (const float*)d_in[3];
    const float* bk = (const float*)d_in[4];
    const float* wv = (const float*)d_in[5];
    const float* bv = (const float*)d_in[6];
    const float* wo = (const float*)d_in[7];
    const float* bo = (const float*)d_in[8];

    float* out = (float*)d_out;                       // [T,B,E]
    float* avg = out + (size_t)TGT*BSZ*E;             // [B,T,T]

    dim3 t256(256);
    qkv_mma_kernel<<<dim3(E/128, M1/128, 3), t256>>>(query, wq, wk, wv);
    qkv_epi_kernel<<<dim3(M1*E/1024, 1, 3), t256>>>(bq, bk, bv);
    scores_mma_kernel<<<dim3(TGT/128, TGT/128, NBH), t256>>>();
    softmax_avg_kernel<<<dim3(TGT, BSZ), t256>>>(avg);
    ctx_mma_kernel<<<dim3(TGT/128, 1, NBH), t256>>>();
    outproj_mma_kernel<<<dim3(E/128, M1/128, 1), t256>>>(wo);
    outproj_epi_kernel<<<dim3(M1*E/1024, 1, 1), t256>>>(bo, out);
}

// round 15
// speedup vs baseline: 1.4347x; 1.0066x over previous
#include <cuda_runtime.h>
#include <mma.h>
#include <math.h>

using namespace nvcuda;

#define TGT 2048
#define BSZ 4
#define E   1024
#define H   16
#define HD  64
#define M1  (TGT*BSZ)   // 8192
#define NBH (BSZ*H)     // 64

// ---- scratch (static device globals; no allocation allowed) ----
__device__ float g_q[(size_t)NBH*TGT*HD];       // [B,H,T,HD]
__device__ float g_k[(size_t)NBH*TGT*HD];
__device__ float g_v[(size_t)NBH*TGT*HD];
__device__ float g_ctx[(size_t)M1*E];           // [T,B,E]
__device__ float g_P[(size_t)NBH*TGT*TGT];      // [B,H,T,T] 1GiB
__device__ float g_tmp[(size_t)3*M1*E];         // raw GEMM staging (100MB)

// ============================================================
// tf32 WMMA NT GEMM, 2-stage double-buffered pipeline.
// C[m,n] = sum_k A[m,k]*B[n,k]; block tile 128x128, K-tile 32,
// 256 threads = 8 warps (4M x 2N), warp tile 32x64.
// Prefetch next K-tile to registers during MMA; RN tf32 convert
// on smem store; ONE __syncthreads per K-tile.
// k-accumulation order identical to Round-13 kernel.
// Dynamic smem: 2*(128*40)*2 matrices * 4B = 81920 B.
// ============================================================

#define NT_SMEM_BYTES  (2*128*40*2*4)
#define CTX_SMEM_BYTES ((2*128*40 + 2*32*72)*4)

#define MMA_NT_LOOP_DB(APTR, LDA, BPTR, LDB, KTOT)                              \
    extern __shared__ float sm_[];                                              \
    float* As = sm_;                 /* [2][128][40] */                         \
    float* Bs = sm_ + 2*128*40;      /* [2][128][40] */                         \
    const int tid  = threadIdx.x;                                               \
    const int warp = tid >> 5;                                                  \
    const int wm   = warp & 3;       /* m0 = wm*32 */                           \
    const int wn   = warp >> 2;      /* n0 = wn*64 */                           \
    const int lr   = tid >> 1;       /* loader row 0..127 */                    \
    const int lc   = (tid & 1) << 4; /* 0 or 16 */                              \
    wmma::fragment<wmma::accumulator,16,16,8,float> acc[2][4];                  \
    _Pragma("unroll")                                                           \
    for (int i=0;i<2;i++)                                                       \
        _Pragma("unroll")                                                       \
        for (int j=0;j<4;j++) wmma::fill_fragment(acc[i][j], 0.0f);             \
    float a_reg[16], b_reg[16];                                                 \
    _Pragma("unroll")                                                           \
    for (int q = 0; q < 4; q++) {                                               \
        *(float4*)(a_reg+q*4) = *(const float4*)((APTR) + (size_t)(mBase+lr)*(LDA) + lc + q*4); \
        *(float4*)(b_reg+q*4) = *(const float4*)((BPTR) + (size_t)(nBase+lr)*(LDB) + lc + q*4); \
    }                                                                           \
    _Pragma("unroll")                                                           \
    for (int q = 0; q < 16; q++) {                                              \
        As[lr*40 + lc + q] = wmma::__float_to_tf32(a_reg[q]);                   \
        Bs[lr*40 + lc + q] = wmma::__float_to_tf32(b_reg[q]);                   \
    }                                                                           \
    __syncthreads();                                                            \
    int cur = 0;                                                                \
    for (int k0 = 0; k0 < (KTOT); k0 += 32) {                                   \
        const bool more = (k0 + 32) < (KTOT);                                   \
        if (more) {                                                             \
            _Pragma("unroll")                                                   \
            for (int q = 0; q < 4; q++) {                                       \
                *(float4*)(a_reg+q*4) = *(const float4*)((APTR) + (size_t)(mBase+lr)*(LDA) + k0+32 + lc + q*4); \
                *(float4*)(b_reg+q*4) = *(const float4*)((BPTR) + (size_t)(nBase+lr)*(LDB) + k0+32 + lc + q*4); \
            }                                                                   \
        }                                                                       \
        const float* Ac = As + cur*5120;                                        \
        const float* Bc = Bs + cur*5120;                                        \
        _Pragma("unroll")                                                       \
        for (int kk = 0; kk < 32; kk += 8) {                                    \
            wmma::fragment<wmma::matrix_a,16,16,8,wmma::precision::tf32,wmma::row_major> af[2]; \
            wmma::fragment<wmma::matrix_b,16,16,8,wmma::precision::tf32,wmma::col_major> bf[4]; \
            _Pragma("unroll")                                                   \
            for (int i=0;i<2;i++) wmma::load_matrix_sync(af[i], Ac + (wm*32+i*16)*40 + kk, 40); \
            _Pragma("unroll")                                                   \
            for (int j=0;j<4;j++) wmma::load_matrix_sync(bf[j], Bc + (wn*64+j*16)*40 + kk, 40); \
            _Pragma("unroll")                                                   \
            for (int i=0;i<2;i++)                                               \
                _Pragma("unroll")                                               \
                for (int j=0;j<4;j++)                                           \
                    wmma::mma_sync(acc[i][j], af[i], bf[j], acc[i][j]);         \
        }                                                                       \
        if (more) {                                                             \
            float* An = As + (cur^1)*5120;                                      \
            float* Bn = Bs + (cur^1)*5120;                                      \
            _Pragma("unroll")                                                   \
            for (int q = 0; q < 16; q++) {                                      \
                An[lr*40 + lc + q] = wmma::__float_to_tf32(a_reg[q]);           \
                Bn[lr*40 + lc + q] = wmma::__float_to_tf32(b_reg[q]);           \
            }                                                                   \
        }                                                                       \
        __syncthreads();                                                        \
        cur ^= 1;                                                               \
    }

// ---- kernel 1a: QKV GEMM -> g_tmp (raw, row-major [M1][E] per matrix) ----
__global__ __launch_bounds__(256) void qkv_mma_kernel(
    const float* __restrict__ x,
    const float* __restrict__ wq, const float* __restrict__ wk,
    const float* __restrict__ wv)
{
    const int which = blockIdx.z;
    const float* w = (which==0) ? wq : (which==1) ? wk : wv;
    float* outp = g_tmp + (size_t)which * M1 * E;

    const int mBase = blockIdx.y * 128, nBase = blockIdx.x * 128;
    MMA_NT_LOOP_DB(x, E, w, E, E)

    #pragma unroll
    for (int i=0;i<2;i++)
        #pragma unroll
        for (int j=0;j<4;j++)
            wmma::store_matrix_sync(
                outp + (size_t)(mBase + wm*32 + i*16)*E + nBase + wn*64 + j*16,
                acc[i][j], E, wmma::mem_row_major);
}

// ---- kernel 1b: QKV epilogue: bias + scale + scatter to [B,H,T,HD] ----
__global__ __launch_bounds__(256) void qkv_epi_kernel(
    const float* __restrict__ bq, const float* __restrict__ bk,
    const float* __restrict__ bv)
{
    const int which = blockIdx.z;
    const float* bias = (which==0) ? bq : (which==1) ? bk : bv;
    const float* tmp  = g_tmp + (size_t)which * M1 * E;
    float* outp       = (which==0) ? g_q : (which==1) ? g_k : g_v;
    const float scale = (which==0) ? 0.125f : 1.0f;   // HD^-0.5

    const int idx = (blockIdx.x * 256 + threadIdx.x) * 4;   // multiple of 4
    const int m = idx / E, n = idx % E;
    const int t = m >> 2, b = m & 3;          // m = t*BSZ + b
    const int h = n >> 6, d = n & 63;         // 4 consecutive d, same head

    const float4 v4 = *(const float4*)(tmp + (size_t)m*E + n);
    const float4 b4 = *(const float4*)(bias + n);
    float4 o4;
    o4.x = (v4.x + b4.x) * scale;
    o4.y = (v4.y + b4.y) * scale;
    o4.z = (v4.z + b4.z) * scale;
    o4.w = (v4.w + b4.w) * scale;
    *(float4*)(outp + ((size_t)(b*H + h)*TGT + t)*HD + d) = o4;
}

// ---- kernel 2: scores = q @ k^T per (b,h), direct store to g_P ----
__global__ __launch_bounds__(256) void scores_mma_kernel()
{
    const int bh = blockIdx.z;
    const float* A  = g_q + (size_t)bh * TGT * HD;
    const float* Bm = g_k + (size_t)bh * TGT * HD;
    float* P = g_P + (size_t)bh * TGT * TGT;

    const int mBase = blockIdx.y * 128, nBase = blockIdx.x * 128;
    MMA_NT_LOOP_DB(A, HD, Bm, HD, HD)

    #pragma unroll
    for (int i=0;i<2;i++)
        #pragma unroll
        for (int j=0;j<4;j++)
            wmma::store_matrix_sync(
                P + (size_t)(mBase + wm*32 + i*16)*TGT + nBase + wn*64 + j*16,
                acc[i][j], TGT, wmma::mem_row_major);
}

// ---- kernel 3: row softmax of P (in place) + head-avg (unchanged) ----
__global__ __launch_bounds__(256) void softmax_avg_kernel(float* __restrict__ avg_out)
{
    const int t = blockIdx.x, b = blockIdx.y;
    const int tid = threadIdx.x;
    __shared__ float sred[8];

    float accAvg[8];
    #pragma unroll
    for (int j=0;j<8;j++) accAvg[j] = 0.0f;

    for (int h = 0; h < H; h++) {
        float* row = g_P + ((size_t)((b*H + h)*TGT) + t) * TGT;
        float r[8];
        #pragma unroll
        for (int j=0;j<8;j++) r[j] = row[tid + j*256];

        float m = r[0];
        #pragma unroll
        for (int j=1;j<8;j++) m = fmaxf(m, r[j]);
        #pragma unroll
        for (int o=16;o>0;o>>=1) m = fmaxf(m, __shfl_xor_sync(0xffffffffu, m, o));
        if ((tid & 31) == 0) sred[tid >> 5] = m;
        __syncthreads();
        if (tid < 32) {
            float w = (tid < 8) ? sred[tid] : -INFINITY;
            #pragma unroll
            for (int o=4;o>0;o>>=1) w = fmaxf(w, __shfl_xor_sync(0xffffffffu, w, o));
            if (tid == 0) sred[0] = w;
        }
        __syncthreads();
        m = sred[0];
        __syncthreads();

        float s = 0.0f;
        #pragma unroll
        for (int j=0;j<8;j++) { r[j] = __expf(r[j] - m); s += r[j]; }
        #pragma unroll
        for (int o=16;o>0;o>>=1) s += __shfl_xor_sync(0xffffffffu, s, o);
        if ((tid & 31) == 0) sred[tid >> 5] = s;
        __syncthreads();
        if (tid < 32) {
            float w = (tid < 8) ? sred[tid] : 0.0f;
            #pragma unroll
            for (int o=4;o>0;o>>=1) w += __shfl_xor_sync(0xffffffffu, w, o);
            if (tid == 0) sred[0] = w;
        }
        __syncthreads();
        s = sred[0];
        __syncthreads();

        const float inv = 1.0f / s;
        #pragma unroll
        for (int j=0;j<8;j++) {
            const float p = r[j] * inv;
            row[tid + j*256] = p;
            accAvg[j] += p;
        }
    }
    const float invH = 1.0f / (float)H;
    #pragma unroll
    for (int j=0;j<8;j++)
        avg_out[((size_t)b*TGT + t)*TGT + tid + j*256] = accAvg[j] * invH;
}

// ---- kernel 4: ctx = P @ V (NN, K=TGT, N=HD=64), double-buffered ----
// tile 128(m) x 64(n), K-tile 32; 8 warps = 4M x 2N, warp 32x32
__global__ __launch_bounds__(256) void ctx_mma_kernel()
{
    const int bh = blockIdx.z;
    const int b = bh / H, h = bh % H;
    const float* P = g_P + (size_t)bh * TGT * TGT;
    const float* V = g_v + (size_t)bh * TGT * HD;

    extern __shared__ float sm_[];
    float* As = sm_;                 // [2][128][40]
    float* Bs = sm_ + 2*128*40;      // [2][32][72]

    const int tid  = threadIdx.x;
    const int warp = tid >> 5;
    const int wm   = warp & 3;        // m0 = wm*32
    const int wn   = warp >> 2;       // n0 = wn*32
    const int lr   = tid >> 1;        // A loader row 0..127
    const int lc   = (tid & 1) << 4;  // 0 or 16
    const int vk   = tid >> 3;        // V loader row 0..31
    const int vn   = (tid & 7) << 3;  // V loader col 0,8,...,56
    const int mBase = blockIdx.x * 128;

    wmma::fragment<wmma::accumulator,16,16,8,float> acc[2][2];
    #pragma unroll
    for (int i=0;i<2;i++)
        #pragma unroll
        for (int j=0;j<2;j++) wmma::fill_fragment(acc[i][j], 0.0f);

    float a_reg[16], b_reg[8];
    #pragma unroll
    for (int q = 0; q < 4; q++)
        *(float4*)(a_reg+q*4) = *(const float4*)(P + (size_t)(mBase+lr)*TGT + lc + q*4);
    #pragma unroll
    for (int q = 0; q < 2; q++)
        *(float4*)(b_reg+q*4) = *(const float4*)(V + (size_t)vk*HD + vn + q*4);
    #pragma unroll
    for (int q = 0; q < 16; q++) As[lr*40 + lc + q] = wmma::__float_to_tf32(a_reg[q]);
    #pragma unroll
    for (int q = 0; q < 8; q++)  Bs[vk*72 + vn + q] = wmma::__float_to_tf32(b_reg[q]);
    __syncthreads();

    int cur = 0;
    for (int k0 = 0; k0 < TGT; k0 += 32) {
        const bool more = (k0 + 32) < TGT;
        if (more) {
            #pragma unroll
            for (int q = 0; q < 4; q++)
                *(float4*)(a_reg+q*4) = *(const float4*)(P + (size_t)(mBase+lr)*TGT + k0+32 + lc + q*4);
            #pragma unroll
            for (int q = 0; q < 2; q++)
                *(float4*)(b_reg+q*4) = *(const float4*)(V + (size_t)(k0+32+vk)*HD + vn + q*4);
        }
        const float* Ac = As + cur*5120;
        const float* Bc = Bs + cur*2304;
        #pragma unroll
        for (int kk = 0; kk < 32; kk += 8) {
            wmma::fragment<wmma::matrix_a,16,16,8,wmma::precision::tf32,wmma::row_major> af[2];
            wmma::fragment<wmma::matrix_b,16,16,8,wmma::precision::tf32,wmma::row_major> bf[2];
            #pragma unroll
            for (int i=0;i<2;i++) wmma::load_matrix_sync(af[i], Ac + (wm*32+i*16)*40 + kk, 40);
            #pragma unroll
            for (int j=0;j<2;j++) wmma::load_matrix_sync(bf[j], Bc + kk*72 + wn*32 + j*16, 72);
            #pragma unroll
            for (int i=0;i<2;i++)
                #pragma unroll
                for (int j=0;j<2;j++)
                    wmma::mma_sync(acc[i][j], af[i], bf[j], acc[i][j]);
        }
        if (more) {
            float* An = As + (cur^1)*5120;
            float* Bn = Bs + (cur^1)*2304;
            #pragma unroll
            for (int q = 0; q < 16; q++) An[lr*40 + lc + q] = wmma::__float_to_tf32(a_reg[q]);
            #pragma unroll
            for (int q = 0; q < 8; q++)  Bn[vk*72 + vn + q] = wmma::__float_to_tf32(b_reg[q]);
        }
        __syncthreads();
        cur ^= 1;
    }
    // store: g_ctx[(q*BSZ+b)*E + h*HD + d], row stride BSZ*E
    #pragma unroll
    for (int i=0;i<2;i++)
        #pragma unroll
        for (int j=0;j<2;j++)
            wmma::store_matrix_sync(
                g_ctx + ((size_t)(mBase + wm*32 + i*16)*BSZ + b)*E + h*HD + wn*32 + j*16,
                acc[i][j], BSZ*E, wmma::mem_row_major);
}

// ---- kernel 5a: outproj GEMM -> g_tmp[0] raw ----
__global__ __launch_bounds__(256) void outproj_mma_kernel(const float* __restrict__ wo)
{
    float* outp = g_tmp;
    const int mBase = blockIdx.y * 128, nBase = blockIdx.x * 128;
    MMA_NT_LOOP_DB(g_ctx, E, wo, E, E)

    #pragma unroll
    for (int i=0;i<2;i++)
        #pragma unroll
        for (int j=0;j<4;j++)
            wmma::store_matrix_sync(
                outp + (size_t)(mBase + wm*32 + i*16)*E + nBase + wn*64 + j*16,
                acc[i][j], E, wmma::mem_row_major);
}

// ---- kernel 5b: outproj epilogue: + bias -> out ----
__global__ __launch_bounds__(256) void outproj_epi_kernel(
    const float* __restrict__ bo, float* __restrict__ out)
{
    const int idx = (blockIdx.x * 256 + threadIdx.x) * 4;
    const int n = idx % E;
    const float4 v4 = *(const float4*)(g_tmp + idx);
    const float4 b4 = *(const float4*)(bo + n);
    float4 o4;
    o4.x = v4.x + b4.x; o4.y = v4.y + b4.y;
    o4.z = v4.z + b4.z; o4.w = v4.w + b4.w;
    *(float4*)(out + idx) = o4;
}

extern "C" void kernel_launch(void* const* d_in, const int* in_sizes, int n_in,
                              void* d_out, int out_size)
{
    (void)in_sizes; (void)n_in; (void)out_size;
    const float* query = (const float*)d_in[0];
    const float* wq = (const float*)d_in[1];
    const float* bq = (const float*)d_in[2];
    const float* wk = (const float*)d_in[3];
    const float* bk = (const float*)d_in[4];
    const float* wv = (const float*)d_in[5];
    const float* bv = (const float*)d_in[6];
    const float* wo = (const float*)d_in[7];
    const float* bo = (const float*)d_in[8];

    float* out = (float*)d_out;                       // [T,B,E]
    float* avg = out + (size_t)TGT*BSZ*E;             // [B,T,T]

    // opt-in to >48KB dynamic smem (idempotent; not an allocation)
    cudaFuncSetAttribute(qkv_mma_kernel,     cudaFuncAttributeMaxDynamicSharedMemorySize, NT_SMEM_BYTES);
    cudaFuncSetAttribute(scores_mma_kernel,  cudaFuncAttributeMaxDynamicSharedMemorySize, NT_SMEM_BYTES);
    cudaFuncSetAttribute(outproj_mma_kernel, cudaFuncAttributeMaxDynamicSharedMemorySize, NT_SMEM_BYTES);
    cudaFuncSetAttribute(ctx_mma_kernel,     cudaFuncAttributeMaxDynamicSharedMemorySize, CTX_SMEM_BYTES);

    dim3 t256(256);
    qkv_mma_kernel<<<dim3(E/128, M1/128, 3), t256, NT_SMEM_BYTES>>>(query, wq, wk, wv);
    qkv_epi_kernel<<<dim3(M1*E/1024, 1, 3), t256>>>(bq, bk, bv);
    scores_mma_kernel<<<dim3(TGT/128, TGT/128, NBH), t256, NT_SMEM_BYTES>>>();
    softmax_avg_kernel<<<dim3(TGT, BSZ), t256>>>(avg);
    ctx_mma_kernel<<<dim3(TGT/128, 1, NBH), t256, CTX_SMEM_BYTES>>>();
    outproj_mma_kernel<<<dim3(E/128, M1/128, 1), t256, NT_SMEM_BYTES>>>(wo);
    outproj_epi_kernel<<<dim3(M1*E/1024, 1, 1), t256>>>(bo, out);
}